// round 10
// baseline (speedup 1.0000x reference)
#include <cuda_runtime.h>
#include <cuda_fp16.h>
#include <cuda_fp8.h>
#include <cstdint>
#include <cstddef>

#define NMAX 50048
#define EMAX 1700000
#define FDIM 128
#define GNUM 64
#define HID2 64
#define OUTD 10

// ---------------- scratch ----------------
__device__ __align__(16) unsigned char  g_hw8 [NMAX * FDIM];  // h rows, e4m3 (scaled)
__device__ __align__(16) float g_acc[NMAX * FDIM];
__device__ __align__(16) float g_als[NMAX * 4];
__device__ __align__(16) float g_ald[NMAX * 4];
__device__ __align__(16) float g_colsum[GNUM * FDIM];
__device__ __align__(16) float g_num[GNUM * FDIM];
__device__ __align__(16) float g_gatesum[GNUM];
__device__ __align__(16) float g_hg [GNUM * FDIM];
__device__ int g_src32[EMAX];
__device__ int g_dst32[EMAX];
__device__ int g_deg[NMAX];
__device__ int g_off[NMAX + 1];
__device__ int g_cur[NMAX];
__device__ int g_csr[EMAX];
__device__ int g_bsum[64];
__device__ int g_idx64;

__device__ __forceinline__ int load_idx(const void* p, long long i, int f64) {
    return f64 ? (int)((const long long*)p)[i] : ((const int*)p)[i];
}
__device__ __forceinline__ void red_add_v4(float* ptr, float a, float b, float c, float d) {
    asm volatile("red.global.add.v4.f32 [%0], {%1,%2,%3,%4};"
                 :: "l"(ptr), "f"(a), "f"(b), "f"(c), "f"(d) : "memory");
}
// fp8 row loader: lane covers features [4*lane, 4*lane+4)
__device__ __forceinline__ float4 ldrow8(int n, int lane) {
    unsigned int raw = ((const unsigned int*)(g_hw8 + (size_t)n * 128))[lane];
    __nv_fp8x2_storage_t lo = (__nv_fp8x2_storage_t)(raw & 0xffffu);
    __nv_fp8x2_storage_t hi = (__nv_fp8x2_storage_t)(raw >> 16);
    __half2_raw h0 = __nv_cvt_fp8x2_to_halfraw2(lo, __NV_E4M3);
    __half2_raw h1 = __nv_cvt_fp8x2_to_halfraw2(hi, __NV_E4M3);
    float2 f0 = __half22float2(*reinterpret_cast<__half2*>(&h0));
    float2 f1 = __half22float2(*reinterpret_cast<__half2*>(&h1));
    return make_float4(f0.x, f0.y, f1.x, f1.y);
}

// zero + index-width probe (merged)
__global__ void k_zero_pre(const void* ei, int N) {
    int t = blockIdx.x * blockDim.x + threadIdx.x;
    if (t == 0) {
        const int* w = (const int*)ei;
        int f = 1;
        for (int i = 0; i < 64; i++) if (w[2 * i + 1] != 0) { f = 0; break; }
        g_idx64 = f;
    }
    if (t < N) g_deg[t] = 0;
    if (t < GNUM * FDIM) { g_colsum[t] = 0.f; g_num[t] = 0.f; g_hg[t] = 0.f; }
    if (t < GNUM) g_gatesum[t] = 0.f;
}

__global__ void k_prep(const void* __restrict__ ei, long long E) {
    long long t = (long long)blockIdx.x * blockDim.x + threadIdx.x;
    if (t >= E) return;
    int f64 = g_idx64;
    int s = load_idx(ei, t, f64);
    int d = load_idx(ei, E + t, f64);
    g_src32[t] = s;
    g_dst32[t] = d;
    atomicAdd(&g_deg[d], 1);
}

// ---- multi-block exclusive scan ----
__global__ void k_scan1(int N) {
    __shared__ int wsum[32];
    int b = blockIdx.x;
    int i = b * 1024 + threadIdx.x;
    int lane = threadIdx.x & 31, w = threadIdx.x >> 5;
    int v = (i < N) ? g_deg[i] : 0;
    int x = v;
#pragma unroll
    for (int off = 1; off < 32; off <<= 1) {
        int y = __shfl_up_sync(0xffffffffu, x, off);
        if (lane >= off) x += y;
    }
    if (lane == 31) wsum[w] = x;
    __syncthreads();
    if (w == 0) {
        int s = wsum[lane];
#pragma unroll
        for (int off = 1; off < 32; off <<= 1) {
            int y = __shfl_up_sync(0xffffffffu, s, off);
            if (lane >= off) s += y;
        }
        wsum[lane] = s;
    }
    __syncthreads();
    int excl = x - v + (w ? wsum[w - 1] : 0);
    if (i < N) g_off[i] = excl;
    if (threadIdx.x == 1023) g_bsum[b] = excl + v;
}

__global__ void k_scan3(int nb, int N) {
    __shared__ int s_off, s_tot;
    if (threadIdx.x < 32) {
        int lane = threadIdx.x;
        int v0 = (lane < nb) ? g_bsum[lane] : 0;
        int v1 = (lane + 32 < nb) ? g_bsum[lane + 32] : 0;
        int pre = 0, tot = 0;
        for (int j = 0; j < 64; j++) {
            int vj = __shfl_sync(0xffffffffu, (j < 32) ? v0 : v1, j & 31);
            if (j < (int)blockIdx.x) pre += vj;
            tot += vj;
        }
        if (lane == 0) { s_off = pre; s_tot = tot; }
    }
    __syncthreads();
    int i = blockIdx.x * 1024 + threadIdx.x;
    if (i < N) {
        int o = g_off[i] + s_off;
        g_off[i] = o;
        g_cur[i] = o;
    }
    if (blockIdx.x == 0 && threadIdx.x == 0) g_off[N] = s_tot;
}

__global__ void k_fill(long long E) {
    long long t = (long long)blockIdx.x * blockDim.x + threadIdx.x;
    if (t >= E) return;
    int s = g_src32[t];
    int d = g_dst32[t];
    int pos = atomicAdd(&g_cur[d], 1);
    g_csr[pos] = s;
}

// GEMM core on an smem tile; stores rows as fp8(acc*scale) + als/ald (fp32).
__device__ __forceinline__ void gemm_tile(const float* sx, const float* __restrict__ W,
                                          const float* __restrict__ a_src,
                                          const float* __restrict__ a_dst,
                                          int row0, int N, float scale) {
    int col = threadIdx.x;
    unsigned long long acc2[16];
#pragma unroll
    for (int r = 0; r < 16; r++) acc2[r] = 0ull;
#pragma unroll 4
    for (int k = 0; k < 128; k += 4) {
        float w0 = W[(k + 0) * 128 + col];
        float w1 = W[(k + 1) * 128 + col];
        float w2 = W[(k + 2) * 128 + col];
        float w3 = W[(k + 3) * 128 + col];
        unsigned long long wp01, wp23;
        asm("mov.b64 %0,{%1,%2};" : "=l"(wp01) : "f"(w0), "f"(w1));
        asm("mov.b64 %0,{%1,%2};" : "=l"(wp23) : "f"(w2), "f"(w3));
#pragma unroll
        for (int r = 0; r < 16; r++) {
            ulonglong2 a = *(const ulonglong2*)&sx[r * 128 + k];
            asm("fma.rn.f32x2 %0,%1,%2,%0;" : "+l"(acc2[r]) : "l"(a.x), "l"(wp01));
            asm("fma.rn.f32x2 %0,%1,%2,%0;" : "+l"(acc2[r]) : "l"(a.y), "l"(wp23));
        }
    }
    float a_s = a_src[col];
    float a_d = a_dst[col];
    int wrp = threadIdx.x >> 5, lane = threadIdx.x & 31;
#pragma unroll
    for (int r = 0; r < 16; r++) {
        float lo, hi;
        asm("mov.b64 {%0,%1},%2;" : "=f"(lo), "=f"(hi) : "l"(acc2[r]));
        float acc = lo + hi;
        int row = row0 + r;
        float ps = acc * a_s;
        float pd = acc * a_d;
#pragma unroll
        for (int off = 16; off; off >>= 1) {
            ps += __shfl_xor_sync(0xffffffffu, ps, off);
            pd += __shfl_xor_sync(0xffffffffu, pd, off);
        }
        if (row < N) {
            g_hw8[(size_t)row * 128 + col] =
                __nv_cvt_float_to_fp8(acc * scale, __NV_SATFINITE, __NV_E4M3);
            if (lane == 0) {
                g_als[row * 4 + wrp] = ps;
                g_ald[row * 4 + wrp] = pd;
            }
        }
    }
}

// ---------------- layer-1 GEMM (input x) ----------------
__global__ void k_gemm(const float* __restrict__ A, const float* __restrict__ W,
                       const float* __restrict__ a_src, const float* __restrict__ a_dst,
                       int N, float scale) {
    __shared__ __align__(16) float sx[16 * 128];
    int row0 = blockIdx.x * 16;
    float4* sx4 = (float4*)sx;
    const float4* A4 = (const float4*)A;
    for (int i = threadIdx.x; i < 512; i += 128) {
        int r = i >> 5;
        if (row0 + r < N) sx4[i] = A4[(size_t)(row0 + r) * 32 + (i & 31)];
        else sx4[i] = make_float4(0.f, 0.f, 0.f, 0.f);
    }
    __syncthreads();
    gemm_tile(sx, W, a_src, a_dst, row0, N, scale);
}

// ---------------- fused: layer-1 ngp + layer-2 GEMM ----------------
__global__ void k_ngp_gemm(const void* __restrict__ batch,
                           const float* __restrict__ gate_w, const float* __restrict__ gate_b,
                           const float* __restrict__ W,
                           const float* __restrict__ a_src, const float* __restrict__ a_dst,
                           int N, float scale) {
    __shared__ __align__(16) float sx[16 * 128];
    __shared__ float sge[16];
    __shared__ int sgid[16];
    __shared__ float spart[16][4];
    int row0 = blockIdx.x * 16;
    int tid = threadIdx.x;
    int wrp = tid >> 5, lane = tid & 31;
    int f64 = g_idx64;
    float4* sx4 = (float4*)sx;
    const float4* acc4 = (const float4*)g_acc;
    for (int i = tid; i < 512; i += 128) {
        int r = i >> 5, c = i & 31;
        int row = row0 + r;
        if (row < N) {
            int g = load_idx(batch, row, f64);
            if (c == 0) sgid[r] = g;
            float4 e = acc4[(size_t)row * 32 + c];
            float4 cs = ((const float4*)(g_colsum + g * 128))[c];
            sx4[i] = make_float4(__fdividef(e.x, cs.x), __fdividef(e.y, cs.y),
                                 __fdividef(e.z, cs.z), __fdividef(e.w, cs.w));
        } else {
            if (c == 0) sgid[r] = 0;
            sx4[i] = make_float4(0.f, 0.f, 0.f, 0.f);
        }
    }
    __syncthreads();
    float gwv = gate_w[tid];
#pragma unroll
    for (int r = 0; r < 16; r++) {
        float p = sx[r * 128 + tid] * gwv;
#pragma unroll
        for (int off = 16; off; off >>= 1) p += __shfl_xor_sync(0xffffffffu, p, off);
        if (lane == 0) spart[r][wrp] = p;
    }
    __syncthreads();
    if (tid < 16) {
        float p = spart[tid][0] + spart[tid][1] + spart[tid][2] + spart[tid][3] + gate_b[0];
        float ge = __expf(p);
        sge[tid] = ge;
        if (row0 + tid < N) atomicAdd(&g_gatesum[sgid[tid]], ge);
    }
    __syncthreads();
#pragma unroll
    for (int rr = 0; rr < 4; rr++) {
        int r = wrp + rr * 4;
        if (row0 + r < N) {
            float ge = sge[r];
            float4 hs = sx4[r * 32 + lane];
            red_add_v4(g_num + sgid[r] * 128 + lane * 4,
                       ge * hs.x, ge * hs.y, ge * hs.z, ge * hs.w);
        }
    }
    gemm_tile(sx, W, a_src, a_dst, row0, N, scale);
}

// ---------------- aggregation: warp per dst, load-first phase split ----------
__global__ void k_agg(const float* __restrict__ bvec, const void* __restrict__ batch,
                      int N, float invscale) {
    int n = blockIdx.x * 8 + (threadIdx.x >> 5);
    int lane = threadIdx.x & 31;
    if (n >= N) return;
    const unsigned FULL = 0xffffffffu;
    int hf = lane >> 3;
    int hq = lane & 3;
    float ald_q = g_ald[n * 4 + hq];
    float lg = g_als[n * 4 + hq] + ald_q;
    lg = lg > 0.f ? lg : 0.2f * lg;
    float wq = __expf(lg);
    float ssum_q = wq;
    float wf = __shfl_sync(FULL, wq, hf);
    float4 v = ldrow8(n, lane);
    float4 acc = make_float4(wf * v.x, wf * v.y, wf * v.z, wf * v.w);

    int beg = g_off[n], end = g_off[n + 1];
    int et = lane >> 2;
    for (int j = beg; j < end; j += 8) {
        int rem = end - j;
        int s_e = (et < rem) ? g_csr[j + et] : 0;
        // phase A: broadcast indices and ISSUE ALL ROW LOADS first
        int s0 = __shfl_sync(FULL, s_e, 0);
        int s1 = __shfl_sync(FULL, s_e, 4);
        int s2 = __shfl_sync(FULL, s_e, 8);
        int s3 = __shfl_sync(FULL, s_e, 12);
        int s4 = __shfl_sync(FULL, s_e, 16);
        int s5 = __shfl_sync(FULL, s_e, 20);
        int s6 = __shfl_sync(FULL, s_e, 24);
        int s7 = __shfl_sync(FULL, s_e, 28);
        float4 u0 = ldrow8(s0, lane);
        float4 u1 = ldrow8(s1, lane);
        float4 u2 = ldrow8(s2, lane);
        float4 u3 = ldrow8(s3, lane);
        float4 u4 = ldrow8(s4, lane);
        float4 u5 = ldrow8(s5, lane);
        float4 u6 = ldrow8(s6, lane);
        float4 u7 = ldrow8(s7, lane);
        // phase B: attention weights (overlaps the in-flight row loads)
        float wv = 0.f;
        if (et < rem) {
            float l = g_als[s_e * 4 + hq] + ald_q;
            l = l > 0.f ? l : 0.2f * l;
            wv = __expf(l);
        }
        ssum_q += wv;
        float w0 = __shfl_sync(FULL, wv, 0 + hf);
        float w1 = __shfl_sync(FULL, wv, 4 + hf);
        float w2 = __shfl_sync(FULL, wv, 8 + hf);
        float w3 = __shfl_sync(FULL, wv, 12 + hf);
        float w4 = __shfl_sync(FULL, wv, 16 + hf);
        float w5 = __shfl_sync(FULL, wv, 20 + hf);
        float w6 = __shfl_sync(FULL, wv, 24 + hf);
        float w7 = __shfl_sync(FULL, wv, 28 + hf);
        acc.x += w0 * u0.x; acc.y += w0 * u0.y; acc.z += w0 * u0.z; acc.w += w0 * u0.w;
        acc.x += w1 * u1.x; acc.y += w1 * u1.y; acc.z += w1 * u1.z; acc.w += w1 * u1.w;
        acc.x += w2 * u2.x; acc.y += w2 * u2.y; acc.z += w2 * u2.z; acc.w += w2 * u2.w;
        acc.x += w3 * u3.x; acc.y += w3 * u3.y; acc.z += w3 * u3.z; acc.w += w3 * u3.w;
        acc.x += w4 * u4.x; acc.y += w4 * u4.y; acc.z += w4 * u4.z; acc.w += w4 * u4.w;
        acc.x += w5 * u5.x; acc.y += w5 * u5.y; acc.z += w5 * u5.z; acc.w += w5 * u5.w;
        acc.x += w6 * u6.x; acc.y += w6 * u6.y; acc.z += w6 * u6.z; acc.w += w6 * u6.w;
        acc.x += w7 * u7.x; acc.y += w7 * u7.y; acc.z += w7 * u7.z; acc.w += w7 * u7.w;
    }
#pragma unroll
    for (int off = 4; off < 32; off <<= 1) ssum_q += __shfl_xor_sync(FULL, ssum_q, off);
    float inv = __fdividef(invscale, __shfl_sync(FULL, ssum_q, hf));

    float4 b = ((const float4*)bvec)[lane];
    float4 u;
    u.x = fmaxf(acc.x * inv + b.x, 0.f);
    u.y = fmaxf(acc.y * inv + b.y, 0.f);
    u.z = fmaxf(acc.z * inv + b.z, 0.f);
    u.w = fmaxf(acc.w * inv + b.w, 0.f);
    float4 ev = make_float4(__expf(u.x), __expf(u.y), __expf(u.z), __expf(u.w));
    ((float4*)(g_acc + (size_t)n * 128))[lane] = ev;
    int g = load_idx(batch, n, g_idx64);
    red_add_v4(g_colsum + g * 128 + lane * 4, ev.x, ev.y, ev.z, ev.w);
}

// ---------------- layer-2: softmax + gate + pool ----------------
__global__ void k_ngp(const void* __restrict__ batch, const float* __restrict__ gate_w,
                      const float* __restrict__ gate_b, int N) {
    int t = blockIdx.x * blockDim.x + threadIdx.x;
    int n = t >> 5, lane = t & 31;
    if (n >= N) return;
    const unsigned FULL = 0xffffffffu;
    int g = load_idx(batch, n, g_idx64);
    float4 e = ((const float4*)(g_acc + (size_t)n * 128))[lane];
    float4 c = ((const float4*)(g_colsum + g * 128))[lane];
    float4 hs = make_float4(__fdividef(e.x, c.x), __fdividef(e.y, c.y),
                            __fdividef(e.z, c.z), __fdividef(e.w, c.w));
    float4 gw = ((const float4*)gate_w)[lane];
    float p = hs.x * gw.x + hs.y * gw.y + hs.z * gw.z + hs.w * gw.w;
#pragma unroll
    for (int off = 16; off; off >>= 1) p += __shfl_xor_sync(FULL, p, off);
    float ge = __expf(p + gate_b[0]);
    red_add_v4(g_num + g * 128 + lane * 4, ge * hs.x, ge * hs.y, ge * hs.z, ge * hs.w);
    if (lane == 0) atomicAdd(&g_gatesum[g], ge);
}

// finalize after layer 1 (also zeroes per-layer accumulators for layer 2)
__global__ void k_fin() {
    int t = blockIdx.x * blockDim.x + threadIdx.x;
    if (t < GNUM * FDIM) {
        g_hg[t] += g_num[t] * __fdividef(1.f, g_gatesum[t >> 7]);
        g_num[t] = 0.f;
        g_colsum[t] = 0.f;
    }
    if (t < GNUM) g_gatesum[t] = 0.f;
}

// ---------------- MLP head (with fused layer-2 finalize) ----------------
__global__ void k_head(const float* __restrict__ lin_w, const float* __restrict__ lin_b,
                       const float* __restrict__ cls_w, const float* __restrict__ cls_b,
                       float* __restrict__ out) {
    int g = blockIdx.x;
    int j = threadIdx.x;
    __shared__ float shg[FDIM];
    __shared__ float sh[HID2];
    float invgs = __fdividef(1.f, g_gatesum[g]);
#pragma unroll
    for (int r = 0; r < 2; r++) {
        int k = j + r * HID2;
        shg[k] = g_hg[g * 128 + k] + g_num[g * 128 + k] * invgs;
    }
    __syncthreads();
    float a = lin_b[j];
#pragma unroll 4
    for (int k = 0; k < 128; k++) a += shg[k] * lin_w[k * HID2 + j];
    sh[j] = fmaxf(a, 0.f);
    __syncthreads();
    if (j < OUTD) {
        float o = cls_b[j];
#pragma unroll
        for (int k = 0; k < HID2; k++) o += sh[k] * cls_w[k * OUTD + j];
        out[g * OUTD + j] = o;
    }
}

// ---------------- launch ----------------
extern "C" void kernel_launch(void* const* d_in, const int* in_sizes, int n_in,
                              void* d_out, int out_size) {
    const float* x      = (const float*)d_in[0];
    const void*  ei     = d_in[1];
    const void*  batch  = d_in[2];
    const float* W1     = (const float*)d_in[3];
    const float* as1    = (const float*)d_in[4];
    const float* ad1    = (const float*)d_in[5];
    const float* b1     = (const float*)d_in[6];
    const float* W2     = (const float*)d_in[7];
    const float* as2    = (const float*)d_in[8];
    const float* ad2    = (const float*)d_in[9];
    const float* b2     = (const float*)d_in[10];
    const float* gate_w = (const float*)d_in[11];
    const float* gate_b = (const float*)d_in[12];
    const float* lin_w  = (const float*)d_in[13];
    const float* lin_b  = (const float*)d_in[14];
    const float* cls_w  = (const float*)d_in[15];
    const float* cls_b  = (const float*)d_in[16];
    float* out = (float*)d_out;

    int N = in_sizes[0] / FDIM;
    long long E = (long long)in_sizes[1] / 2;

    int nodeBlocks = (N + 7) / 8;
    int edgeBlocks = (int)((E + 255) / 256);
    int scanBlocks = (N + 1023) / 1024;
    int gemmBlocks = (N + 15) / 16;
    int zgrid = (N > GNUM * FDIM ? N : GNUM * FDIM);

    k_zero_pre<<<(zgrid + 255) / 256, 256>>>(ei, N);
    k_prep<<<edgeBlocks, 256>>>(ei, E);
    k_scan1<<<scanBlocks, 1024>>>(N);
    k_scan3<<<scanBlocks, 1024>>>(scanBlocks, N);
    k_fill<<<edgeBlocks, 256>>>(E);

    // ---- layer 1 (fp8 rows, scale 1) ----
    k_gemm<<<gemmBlocks, 128>>>(x, W1, as1, ad1, N, 1.0f);
    k_agg<<<nodeBlocks, 256>>>(b1, batch, N, 1.0f);
    // ---- layer-1 pool + layer-2 GEMM (fp8 rows, scale 64) ----
    k_ngp_gemm<<<gemmBlocks, 128>>>(batch, gate_w, gate_b, W2, as2, ad2, N, 64.0f);
    k_fin<<<(GNUM * FDIM + 255) / 256, 256>>>();

    // ---- layer 2 ----
    k_agg<<<nodeBlocks, 256>>>(b2, batch, N, 1.0f / 64.0f);
    k_ngp<<<nodeBlocks, 256>>>(batch, gate_w, gate_b, N);

    // head (fused layer-2 finalize)
    k_head<<<GNUM, HID2>>>(lin_w, lin_b, cls_w, cls_b, out);
}

// round 11
// speedup vs baseline: 1.0971x; 1.0971x over previous
#include <cuda_runtime.h>
#include <cuda_fp16.h>
#include <cuda_fp8.h>
#include <cstdint>
#include <cstddef>

#define NMAX 50048
#define EMAX 1700000
#define FDIM 128
#define GNUM 64
#define HID2 64
#define OUTD 10

// ---------------- scratch ----------------
__device__ __align__(16) unsigned char  g_hw8 [NMAX * FDIM];  // h rows, e4m3 (scaled)
__device__ __align__(16) float g_acc[NMAX * FDIM];
__device__ __align__(16) float g_als[NMAX * 4];
__device__ __align__(16) float g_ald[NMAX * 4];
__device__ __align__(16) float g_colsum[GNUM * FDIM];
__device__ __align__(16) float g_num[GNUM * FDIM];
__device__ __align__(16) float g_gatesum[GNUM];
__device__ __align__(16) float g_hg [GNUM * FDIM];
__device__ int g_src32[EMAX];
__device__ int g_dst32[EMAX];
__device__ int g_deg[NMAX];
__device__ int g_off[NMAX + 1];
__device__ int g_cur[NMAX];
__device__ int g_csr[EMAX];
__device__ int g_bsum[64];
__device__ int g_idx64;

__device__ __forceinline__ int load_idx(const void* p, long long i, int f64) {
    return f64 ? (int)((const long long*)p)[i] : ((const int*)p)[i];
}
__device__ __forceinline__ void red_add_v4(float* ptr, float a, float b, float c, float d) {
    asm volatile("red.global.add.v4.f32 [%0], {%1,%2,%3,%4};"
                 :: "l"(ptr), "f"(a), "f"(b), "f"(c), "f"(d) : "memory");
}
// fp8 row loader: lane covers features [4*lane, 4*lane+4)
__device__ __forceinline__ float4 ldrow8(int n, int lane) {
    unsigned int raw = ((const unsigned int*)(g_hw8 + (size_t)n * 128))[lane];
    __nv_fp8x2_storage_t lo = (__nv_fp8x2_storage_t)(raw & 0xffffu);
    __nv_fp8x2_storage_t hi = (__nv_fp8x2_storage_t)(raw >> 16);
    __half2_raw h0 = __nv_cvt_fp8x2_to_halfraw2(lo, __NV_E4M3);
    __half2_raw h1 = __nv_cvt_fp8x2_to_halfraw2(hi, __NV_E4M3);
    float2 f0 = __half22float2(*reinterpret_cast<__half2*>(&h0));
    float2 f1 = __half22float2(*reinterpret_cast<__half2*>(&h1));
    return make_float4(f0.x, f0.y, f1.x, f1.y);
}

// zero + index-width probe (merged)
__global__ void k_zero_pre(const void* ei, int N) {
    int t = blockIdx.x * blockDim.x + threadIdx.x;
    if (t == 0) {
        const int* w = (const int*)ei;
        int f = 1;
        for (int i = 0; i < 64; i++) if (w[2 * i + 1] != 0) { f = 0; break; }
        g_idx64 = f;
    }
    if (t < N) g_deg[t] = 0;
    if (t < GNUM * FDIM) { g_colsum[t] = 0.f; g_num[t] = 0.f; g_hg[t] = 0.f; }
    if (t < GNUM) g_gatesum[t] = 0.f;
}

__global__ void k_prep(const void* __restrict__ ei, long long E) {
    long long t = (long long)blockIdx.x * blockDim.x + threadIdx.x;
    if (t >= E) return;
    int f64 = g_idx64;
    int s = load_idx(ei, t, f64);
    int d = load_idx(ei, E + t, f64);
    g_src32[t] = s;
    g_dst32[t] = d;
    atomicAdd(&g_deg[d], 1);
}

// ---- multi-block exclusive scan ----
__global__ void k_scan1(int N) {
    __shared__ int wsum[32];
    int b = blockIdx.x;
    int i = b * 1024 + threadIdx.x;
    int lane = threadIdx.x & 31, w = threadIdx.x >> 5;
    int v = (i < N) ? g_deg[i] : 0;
    int x = v;
#pragma unroll
    for (int off = 1; off < 32; off <<= 1) {
        int y = __shfl_up_sync(0xffffffffu, x, off);
        if (lane >= off) x += y;
    }
    if (lane == 31) wsum[w] = x;
    __syncthreads();
    if (w == 0) {
        int s = wsum[lane];
#pragma unroll
        for (int off = 1; off < 32; off <<= 1) {
            int y = __shfl_up_sync(0xffffffffu, s, off);
            if (lane >= off) s += y;
        }
        wsum[lane] = s;
    }
    __syncthreads();
    int excl = x - v + (w ? wsum[w - 1] : 0);
    if (i < N) g_off[i] = excl;
    if (threadIdx.x == 1023) g_bsum[b] = excl + v;
}

__global__ void k_scan3(int nb, int N) {
    __shared__ int s_off, s_tot;
    if (threadIdx.x < 32) {
        int lane = threadIdx.x;
        int v0 = (lane < nb) ? g_bsum[lane] : 0;
        int v1 = (lane + 32 < nb) ? g_bsum[lane + 32] : 0;
        int pre = 0, tot = 0;
        for (int j = 0; j < 64; j++) {
            int vj = __shfl_sync(0xffffffffu, (j < 32) ? v0 : v1, j & 31);
            if (j < (int)blockIdx.x) pre += vj;
            tot += vj;
        }
        if (lane == 0) { s_off = pre; s_tot = tot; }
    }
    __syncthreads();
    int i = blockIdx.x * 1024 + threadIdx.x;
    if (i < N) {
        int o = g_off[i] + s_off;
        g_off[i] = o;
        g_cur[i] = o;
    }
    if (blockIdx.x == 0 && threadIdx.x == 0) g_off[N] = s_tot;
}

__global__ void k_fill(long long E) {
    long long t = (long long)blockIdx.x * blockDim.x + threadIdx.x;
    if (t >= E) return;
    int s = g_src32[t];
    int d = g_dst32[t];
    int pos = atomicAdd(&g_cur[d], 1);
    g_csr[pos] = s;
}

// ---------------- register-tiled GEMM core ----------------
// Block tile: 128 rows x 128 cols, 256 threads, 8 rows x 8 cols per thread.
// Thread cols: {2*cg + 32*j, 2*cg+1 + 32*j}, j=0..3 (pair j lies in head j).
// sx: [128][128] fp32 smem tile (rows). sw: [128][128] fp32 smem W (k-major).
__device__ __forceinline__ void gemm_core(const float* sx, const float* sw,
                                          const float* __restrict__ a_src,
                                          const float* __restrict__ a_dst,
                                          int row0, int N, float scale) {
    int tx = threadIdx.x;
    int cg = tx & 15;
    int rg = tx >> 4;
    int r0 = rg * 8;
    unsigned long long acc2[8][4];
#pragma unroll
    for (int r = 0; r < 8; r++)
#pragma unroll
        for (int j = 0; j < 4; j++) acc2[r][j] = 0ull;

    for (int k = 0; k < 128; k += 2) {
        unsigned long long w0[4], w1[4];
#pragma unroll
        for (int j = 0; j < 4; j++) {
            w0[j] = *(const unsigned long long*)&sw[(k + 0) * 128 + j * 32 + cg * 2];
            w1[j] = *(const unsigned long long*)&sw[(k + 1) * 128 + j * 32 + cg * 2];
        }
#pragma unroll
        for (int r = 0; r < 8; r++) {
            float2 a = *(const float2*)&sx[(r0 + r) * 128 + k];
            unsigned long long da0, da1;
            asm("mov.b64 %0,{%1,%1};" : "=l"(da0) : "f"(a.x));
            asm("mov.b64 %0,{%1,%1};" : "=l"(da1) : "f"(a.y));
#pragma unroll
            for (int j = 0; j < 4; j++) {
                asm("fma.rn.f32x2 %0,%1,%2,%0;" : "+l"(acc2[r][j]) : "l"(da0), "l"(w0[j]));
                asm("fma.rn.f32x2 %0,%1,%2,%0;" : "+l"(acc2[r][j]) : "l"(da1), "l"(w1[j]));
            }
        }
    }
    // epilogue: fp8 store + per-head als/ald
    float as_[8], ad_[8];
#pragma unroll
    for (int j = 0; j < 4; j++) {
        float2 s2 = *(const float2*)&a_src[j * 32 + cg * 2];
        float2 d2 = *(const float2*)&a_dst[j * 32 + cg * 2];
        as_[2 * j] = s2.x; as_[2 * j + 1] = s2.y;
        ad_[2 * j] = d2.x; ad_[2 * j + 1] = d2.y;
    }
#pragma unroll
    for (int r = 0; r < 8; r++) {
        int row = row0 + r0 + r;
        float e[8];
#pragma unroll
        for (int j = 0; j < 4; j++) {
            float lo, hi;
            asm("mov.b64 {%0,%1},%2;" : "=f"(lo), "=f"(hi) : "l"(acc2[r][j]));
            e[2 * j] = lo; e[2 * j + 1] = hi;
        }
        float ps[4], pd[4];
#pragma unroll
        for (int j = 0; j < 4; j++) {
            ps[j] = e[2 * j] * as_[2 * j] + e[2 * j + 1] * as_[2 * j + 1];
            pd[j] = e[2 * j] * ad_[2 * j] + e[2 * j + 1] * ad_[2 * j + 1];
        }
#pragma unroll
        for (int m = 1; m < 16; m <<= 1) {
#pragma unroll
            for (int j = 0; j < 4; j++) {
                ps[j] += __shfl_xor_sync(0xffffffffu, ps[j], m);
                pd[j] += __shfl_xor_sync(0xffffffffu, pd[j], m);
            }
        }
        if (row < N) {
#pragma unroll
            for (int j = 0; j < 4; j++) {
                unsigned short b0 = __nv_cvt_float_to_fp8(e[2 * j] * scale, __NV_SATFINITE, __NV_E4M3);
                unsigned short b1 = __nv_cvt_float_to_fp8(e[2 * j + 1] * scale, __NV_SATFINITE, __NV_E4M3);
                *(unsigned short*)&g_hw8[(size_t)row * 128 + j * 32 + cg * 2] =
                    (unsigned short)(b0 | (b1 << 8));
            }
            if (cg == 0) {
                *(float4*)&g_als[row * 4] = make_float4(ps[0], ps[1], ps[2], ps[3]);
                *(float4*)&g_ald[row * 4] = make_float4(pd[0], pd[1], pd[2], pd[3]);
            }
        }
    }
}

// ---------------- layer-1 GEMM (input x) ----------------
__global__ void __launch_bounds__(256, 1)
k_gemm(const float* __restrict__ A, const float* __restrict__ W,
       const float* __restrict__ a_src, const float* __restrict__ a_dst,
       int N, float scale) {
    extern __shared__ float smem[];
    float* sx = smem;           // 16384 floats
    float* sw = smem + 16384;   // 16384 floats
    int tx = threadIdx.x;
    int row0 = blockIdx.x * 128;
    float4* sx4 = (float4*)sx;
    float4* sw4 = (float4*)sw;
    const float4* A4 = (const float4*)A;
    const float4* W4 = (const float4*)W;
#pragma unroll
    for (int i = tx; i < 4096; i += 256) {
        int r = i >> 5;
        sx4[i] = (row0 + r < N) ? A4[(size_t)(row0 + r) * 32 + (i & 31)]
                                : make_float4(0.f, 0.f, 0.f, 0.f);
        sw4[i] = W4[i];
    }
    __syncthreads();
    gemm_core(sx, sw, a_src, a_dst, row0, N, scale);
}

// ---------------- fused: layer-1 ngp (softmax+gate+pool) + layer-2 GEMM -------
__global__ void __launch_bounds__(256, 1)
k_ngp_gemm(const void* __restrict__ batch, const float* __restrict__ gate_w,
           const float* __restrict__ gate_b, const float* __restrict__ W,
           const float* __restrict__ a_src, const float* __restrict__ a_dst,
           int N, float scale) {
    extern __shared__ float smem[];
    float* sx = smem;
    float* sw = smem + 16384;
    float* sge = smem + 32768;            // 128 floats
    int* sgid = (int*)(smem + 32896);     // 128 ints
    int tx = threadIdx.x;
    int lane = tx & 31;
    int row0 = blockIdx.x * 128;
    int f64 = g_idx64;
    float4* sx4 = (float4*)sx;
    float4* sw4 = (float4*)sw;
    const float4* W4 = (const float4*)W;
    const float4* acc4 = (const float4*)g_acc;
#pragma unroll
    for (int i = tx; i < 4096; i += 256) {
        int r = i >> 5, c = i & 31;
        int row = row0 + r;
        if (row < N) {
            int g = load_idx(batch, row, f64);
            if (c == 0) sgid[r] = g;
            float4 e = acc4[(size_t)row * 32 + c];
            float4 cs = ((const float4*)(g_colsum + g * 128))[c];
            sx4[i] = make_float4(__fdividef(e.x, cs.x), __fdividef(e.y, cs.y),
                                 __fdividef(e.z, cs.z), __fdividef(e.w, cs.w));
        } else {
            if (c == 0) sgid[r] = 0;
            sx4[i] = make_float4(0.f, 0.f, 0.f, 0.f);
        }
        sw4[i] = W4[i];
    }
    __syncthreads();
    // gate logits: warp w handles rows w + 8j
    float4 gw = ((const float4*)gate_w)[lane];
#pragma unroll
    for (int j = 0; j < 16; j++) {
        int r = (tx >> 5) + 8 * j;
        float4 hs = sx4[r * 32 + lane];
        float p = hs.x * gw.x + hs.y * gw.y + hs.z * gw.z + hs.w * gw.w;
#pragma unroll
        for (int m = 16; m; m >>= 1) p += __shfl_xor_sync(0xffffffffu, p, m);
        if (lane == 0) sge[r] = p;
    }
    __syncthreads();
    if (tx < 128) {
        float ge = __expf(sge[tx] + gate_b[0]);
        sge[tx] = ge;
        if (row0 + tx < N) atomicAdd(&g_gatesum[sgid[tx]], ge);
    }
    __syncthreads();
#pragma unroll
    for (int j = 0; j < 16; j++) {
        int r = (tx >> 5) + 8 * j;
        int row = row0 + r;
        if (row < N) {
            float ge = sge[r];
            float4 hs = sx4[r * 32 + lane];
            red_add_v4(g_num + sgid[r] * 128 + lane * 4,
                       ge * hs.x, ge * hs.y, ge * hs.z, ge * hs.w);
        }
    }
    gemm_core(sx, sw, a_src, a_dst, row0, N, scale);
}

// ---------------- aggregation: warp per dst (CSR gather, fp8 rows) ----------
__global__ void k_agg(const float* __restrict__ bvec, const void* __restrict__ batch,
                      int N, float invscale) {
    int n = blockIdx.x * 8 + (threadIdx.x >> 5);
    int lane = threadIdx.x & 31;
    if (n >= N) return;
    const unsigned FULL = 0xffffffffu;
    int hf = lane >> 3;
    int hq = lane & 3;
    float ald_q = g_ald[n * 4 + hq];
    float lg = g_als[n * 4 + hq] + ald_q;
    lg = lg > 0.f ? lg : 0.2f * lg;
    float wq = __expf(lg);
    float ssum_q = wq;
    float wf = __shfl_sync(FULL, wq, hf);
    float4 v = ldrow8(n, lane);
    float4 acc = make_float4(wf * v.x, wf * v.y, wf * v.z, wf * v.w);

    int beg = g_off[n], end = g_off[n + 1];
    for (int j = beg; j < end; j += 8) {
        int rem = end - j;
        int et = lane >> 2;
        int s_e = 0; float wv = 0.f;
        if (et < rem) {
            s_e = g_csr[j + et];
            float l2 = g_als[s_e * 4 + hq] + ald_q;
            l2 = l2 > 0.f ? l2 : 0.2f * l2;
            wv = __expf(l2);
        }
        ssum_q += wv;
#pragma unroll
        for (int t = 0; t < 8; t++) {
            float w = __shfl_sync(FULL, wv, t * 4 + hf);
            int s = __shfl_sync(FULL, s_e, t * 4);
            float4 u = ldrow8(s, lane);
            acc.x += w * u.x; acc.y += w * u.y; acc.z += w * u.z; acc.w += w * u.w;
        }
    }
#pragma unroll
    for (int off = 4; off < 32; off <<= 1) ssum_q += __shfl_xor_sync(FULL, ssum_q, off);
    float inv = __fdividef(invscale, __shfl_sync(FULL, ssum_q, hf));

    float4 b = ((const float4*)bvec)[lane];
    float4 u;
    u.x = fmaxf(acc.x * inv + b.x, 0.f);
    u.y = fmaxf(acc.y * inv + b.y, 0.f);
    u.z = fmaxf(acc.z * inv + b.z, 0.f);
    u.w = fmaxf(acc.w * inv + b.w, 0.f);
    float4 ev = make_float4(__expf(u.x), __expf(u.y), __expf(u.z), __expf(u.w));
    ((float4*)(g_acc + (size_t)n * 128))[lane] = ev;
    int g = load_idx(batch, n, g_idx64);
    red_add_v4(g_colsum + g * 128 + lane * 4, ev.x, ev.y, ev.z, ev.w);
}

// ---------------- layer-2: softmax + gate + pool ----------------
__global__ void k_ngp(const void* __restrict__ batch, const float* __restrict__ gate_w,
                      const float* __restrict__ gate_b, int N) {
    int t = blockIdx.x * blockDim.x + threadIdx.x;
    int n = t >> 5, lane = t & 31;
    if (n >= N) return;
    const unsigned FULL = 0xffffffffu;
    int g = load_idx(batch, n, g_idx64);
    float4 e = ((const float4*)(g_acc + (size_t)n * 128))[lane];
    float4 c = ((const float4*)(g_colsum + g * 128))[lane];
    float4 hs = make_float4(__fdividef(e.x, c.x), __fdividef(e.y, c.y),
                            __fdividef(e.z, c.z), __fdividef(e.w, c.w));
    float4 gw = ((const float4*)gate_w)[lane];
    float p = hs.x * gw.x + hs.y * gw.y + hs.z * gw.z + hs.w * gw.w;
#pragma unroll
    for (int off = 16; off; off >>= 1) p += __shfl_xor_sync(FULL, p, off);
    float ge = __expf(p + gate_b[0]);
    red_add_v4(g_num + g * 128 + lane * 4, ge * hs.x, ge * hs.y, ge * hs.z, ge * hs.w);
    if (lane == 0) atomicAdd(&g_gatesum[g], ge);
}

// finalize after layer 1 (also zeroes per-layer accumulators for layer 2)
__global__ void k_fin() {
    int t = blockIdx.x * blockDim.x + threadIdx.x;
    if (t < GNUM * FDIM) {
        g_hg[t] += g_num[t] * __fdividef(1.f, g_gatesum[t >> 7]);
        g_num[t] = 0.f;
        g_colsum[t] = 0.f;
    }
    if (t < GNUM) g_gatesum[t] = 0.f;
}

// ---------------- MLP head (with fused layer-2 finalize) ----------------
__global__ void k_head(const float* __restrict__ lin_w, const float* __restrict__ lin_b,
                       const float* __restrict__ cls_w, const float* __restrict__ cls_b,
                       float* __restrict__ out) {
    int g = blockIdx.x;
    int j = threadIdx.x;
    __shared__ float shg[FDIM];
    __shared__ float sh[HID2];
    float invgs = __fdividef(1.f, g_gatesum[g]);
#pragma unroll
    for (int r = 0; r < 2; r++) {
        int k = j + r * HID2;
        shg[k] = g_hg[g * 128 + k] + g_num[g * 128 + k] * invgs;
    }
    __syncthreads();
    float a = lin_b[j];
#pragma unroll 4
    for (int k = 0; k < 128; k++) a += shg[k] * lin_w[k * HID2 + j];
    sh[j] = fmaxf(a, 0.f);
    __syncthreads();
    if (j < OUTD) {
        float o = cls_b[j];
#pragma unroll
        for (int k = 0; k < HID2; k++) o += sh[k] * cls_w[k * OUTD + j];
        out[g * OUTD + j] = o;
    }
}

// ---------------- launch ----------------
extern "C" void kernel_launch(void* const* d_in, const int* in_sizes, int n_in,
                              void* d_out, int out_size) {
    const float* x      = (const float*)d_in[0];
    const void*  ei     = d_in[1];
    const void*  batch  = d_in[2];
    const float* W1     = (const float*)d_in[3];
    const float* as1    = (const float*)d_in[4];
    const float* ad1    = (const float*)d_in[5];
    const float* b1     = (const float*)d_in[6];
    const float* W2     = (const float*)d_in[7];
    const float* as2    = (const float*)d_in[8];
    const float* ad2    = (const float*)d_in[9];
    const float* b2     = (const float*)d_in[10];
    const float* gate_w = (const float*)d_in[11];
    const float* gate_b = (const float*)d_in[12];
    const float* lin_w  = (const float*)d_in[13];
    const float* lin_b  = (const float*)d_in[14];
    const float* cls_w  = (const float*)d_in[15];
    const float* cls_b  = (const float*)d_in[16];
    float* out = (float*)d_out;

    int N = in_sizes[0] / FDIM;
    long long E = (long long)in_sizes[1] / 2;

    int nodeBlocks = (N + 7) / 8;
    int edgeBlocks = (int)((E + 255) / 256);
    int scanBlocks = (N + 1023) / 1024;
    int gemmBlocks = (N + 127) / 128;
    int zgrid = (N > GNUM * FDIM ? N : GNUM * FDIM);

    size_t gemm_smem = 32768 * sizeof(float);          // 128 KB
    size_t ngpg_smem = (32768 + 256) * sizeof(float);  // +sge/sgid
    cudaFuncSetAttribute(k_gemm, cudaFuncAttributeMaxDynamicSharedMemorySize, (int)gemm_smem);
    cudaFuncSetAttribute(k_ngp_gemm, cudaFuncAttributeMaxDynamicSharedMemorySize, (int)ngpg_smem);

    k_zero_pre<<<(zgrid + 255) / 256, 256>>>(ei, N);
    k_prep<<<edgeBlocks, 256>>>(ei, E);
    k_scan1<<<scanBlocks, 1024>>>(N);
    k_scan3<<<scanBlocks, 1024>>>(scanBlocks, N);
    k_fill<<<edgeBlocks, 256>>>(E);

    // ---- layer 1 (fp8 rows, scale 1) ----
    k_gemm<<<gemmBlocks, 256, gemm_smem>>>(x, W1, as1, ad1, N, 1.0f);
    k_agg<<<nodeBlocks, 256>>>(b1, batch, N, 1.0f);
    // ---- layer-1 pool + layer-2 GEMM (fp8 rows, scale 64) ----
    k_ngp_gemm<<<gemmBlocks, 256, ngpg_smem>>>(batch, gate_w, gate_b, W2, as2, ad2, N, 64.0f);
    k_fin<<<(GNUM * FDIM + 255) / 256, 256>>>();

    // ---- layer 2 ----
    k_agg<<<nodeBlocks, 256>>>(b2, batch, N, 1.0f / 64.0f);
    k_ngp<<<nodeBlocks, 256>>>(batch, gate_w, gate_b, N);

    // head (fused layer-2 finalize)
    k_head<<<GNUM, HID2>>>(lin_w, lin_b, cls_w, cls_b, out);
}

// round 12
// speedup vs baseline: 1.1423x; 1.0412x over previous
#include <cuda_runtime.h>
#include <cuda_fp16.h>
#include <cuda_fp8.h>
#include <cstdint>
#include <cstddef>

#define NMAX 50048
#define EMAX 1700000
#define FDIM 128
#define GNUM 64
#define HID2 64
#define OUTD 10

// ---------------- scratch ----------------
__device__ __align__(16) unsigned char  g_hw8 [NMAX * FDIM];  // h rows, e4m3 (scaled)
__device__ __align__(16) float g_acc[NMAX * FDIM];
__device__ __align__(16) float g_als[NMAX * 4];
__device__ __align__(16) float g_ald[NMAX * 4];
__device__ __align__(16) float g_colsum[GNUM * FDIM];
__device__ __align__(16) float g_num[GNUM * FDIM];
__device__ __align__(16) float g_gatesum[GNUM];
__device__ __align__(16) float g_hg [GNUM * FDIM];
__device__ int g_src32[EMAX];
__device__ int g_dst32[EMAX];
__device__ int g_deg[NMAX];
__device__ int g_off[NMAX + 1];
__device__ int g_cur[NMAX];
__device__ int g_csr[EMAX];
__device__ int g_bsum[64];
__device__ int g_idx64;

__device__ __forceinline__ int load_idx(const void* p, long long i, int f64) {
    return f64 ? (int)((const long long*)p)[i] : ((const int*)p)[i];
}
__device__ __forceinline__ void red_add_v4(float* ptr, float a, float b, float c, float d) {
    asm volatile("red.global.add.v4.f32 [%0], {%1,%2,%3,%4};"
                 :: "l"(ptr), "f"(a), "f"(b), "f"(c), "f"(d) : "memory");
}
// fp8 row loader: lane covers features [4*lane, 4*lane+4)
__device__ __forceinline__ float4 ldrow8(int n, int lane) {
    unsigned int raw = ((const unsigned int*)(g_hw8 + (size_t)n * 128))[lane];
    __nv_fp8x2_storage_t lo = (__nv_fp8x2_storage_t)(raw & 0xffffu);
    __nv_fp8x2_storage_t hi = (__nv_fp8x2_storage_t)(raw >> 16);
    __half2_raw h0 = __nv_cvt_fp8x2_to_halfraw2(lo, __NV_E4M3);
    __half2_raw h1 = __nv_cvt_fp8x2_to_halfraw2(hi, __NV_E4M3);
    float2 f0 = __half22float2(*reinterpret_cast<__half2*>(&h0));
    float2 f1 = __half22float2(*reinterpret_cast<__half2*>(&h1));
    return make_float4(f0.x, f0.y, f1.x, f1.y);
}

// zero + index-width probe (merged)
__global__ void k_zero_pre(const void* ei, int N) {
    int t = blockIdx.x * blockDim.x + threadIdx.x;
    if (t == 0) {
        const int* w = (const int*)ei;
        int f = 1;
        for (int i = 0; i < 64; i++) if (w[2 * i + 1] != 0) { f = 0; break; }
        g_idx64 = f;
    }
    if (t < N) g_deg[t] = 0;
    if (t < GNUM * FDIM) { g_colsum[t] = 0.f; g_num[t] = 0.f; g_hg[t] = 0.f; }
    if (t < GNUM) g_gatesum[t] = 0.f;
}

__global__ void k_prep(const void* __restrict__ ei, long long E) {
    long long t = (long long)blockIdx.x * blockDim.x + threadIdx.x;
    if (t >= E) return;
    int f64 = g_idx64;
    int s = load_idx(ei, t, f64);
    int d = load_idx(ei, E + t, f64);
    g_src32[t] = s;
    g_dst32[t] = d;
    atomicAdd(&g_deg[d], 1);
}

// ---- multi-block exclusive scan ----
__global__ void k_scan1(int N) {
    __shared__ int wsum[32];
    int b = blockIdx.x;
    int i = b * 1024 + threadIdx.x;
    int lane = threadIdx.x & 31, w = threadIdx.x >> 5;
    int v = (i < N) ? g_deg[i] : 0;
    int x = v;
#pragma unroll
    for (int off = 1; off < 32; off <<= 1) {
        int y = __shfl_up_sync(0xffffffffu, x, off);
        if (lane >= off) x += y;
    }
    if (lane == 31) wsum[w] = x;
    __syncthreads();
    if (w == 0) {
        int s = wsum[lane];
#pragma unroll
        for (int off = 1; off < 32; off <<= 1) {
            int y = __shfl_up_sync(0xffffffffu, s, off);
            if (lane >= off) s += y;
        }
        wsum[lane] = s;
    }
    __syncthreads();
    int excl = x - v + (w ? wsum[w - 1] : 0);
    if (i < N) g_off[i] = excl;
    if (threadIdx.x == 1023) g_bsum[b] = excl + v;
}

__global__ void k_scan3(int nb, int N) {
    __shared__ int s_off, s_tot;
    if (threadIdx.x < 32) {
        int lane = threadIdx.x;
        int v0 = (lane < nb) ? g_bsum[lane] : 0;
        int v1 = (lane + 32 < nb) ? g_bsum[lane + 32] : 0;
        int pre = 0, tot = 0;
        for (int j = 0; j < 64; j++) {
            int vj = __shfl_sync(0xffffffffu, (j < 32) ? v0 : v1, j & 31);
            if (j < (int)blockIdx.x) pre += vj;
            tot += vj;
        }
        if (lane == 0) { s_off = pre; s_tot = tot; }
    }
    __syncthreads();
    int i = blockIdx.x * 1024 + threadIdx.x;
    if (i < N) {
        int o = g_off[i] + s_off;
        g_off[i] = o;
        g_cur[i] = o;
    }
    if (blockIdx.x == 0 && threadIdx.x == 0) g_off[N] = s_tot;
}

__global__ void k_fill(long long E) {
    long long t = (long long)blockIdx.x * blockDim.x + threadIdx.x;
    if (t >= E) return;
    int s = g_src32[t];
    int d = g_dst32[t];
    int pos = atomicAdd(&g_cur[d], 1);
    g_csr[pos] = s;
}

// ---------------- register-tiled GEMM core ----------------
// Block tile: 128 rows x 128 cols, 256 threads, 8 rows x 8 cols per thread.
__device__ __forceinline__ void gemm_core(const float* sx, const float* sw,
                                          const float* __restrict__ a_src,
                                          const float* __restrict__ a_dst,
                                          int row0, int N, float scale) {
    int tx = threadIdx.x;
    int cg = tx & 15;
    int rg = tx >> 4;
    int r0 = rg * 8;
    unsigned long long acc2[8][4];
#pragma unroll
    for (int r = 0; r < 8; r++)
#pragma unroll
        for (int j = 0; j < 4; j++) acc2[r][j] = 0ull;

    for (int k = 0; k < 128; k += 4) {
        unsigned long long w0[4], w1[4], w2[4], w3[4];
#pragma unroll
        for (int j = 0; j < 4; j++) {
            w0[j] = *(const unsigned long long*)&sw[(k + 0) * 128 + j * 32 + cg * 2];
            w1[j] = *(const unsigned long long*)&sw[(k + 1) * 128 + j * 32 + cg * 2];
            w2[j] = *(const unsigned long long*)&sw[(k + 2) * 128 + j * 32 + cg * 2];
            w3[j] = *(const unsigned long long*)&sw[(k + 3) * 128 + j * 32 + cg * 2];
        }
#pragma unroll
        for (int r = 0; r < 8; r++) {
            float4 a = *(const float4*)&sx[(r0 + r) * 128 + k];
            unsigned long long da0, da1, da2, da3;
            asm("mov.b64 %0,{%1,%1};" : "=l"(da0) : "f"(a.x));
            asm("mov.b64 %0,{%1,%1};" : "=l"(da1) : "f"(a.y));
            asm("mov.b64 %0,{%1,%1};" : "=l"(da2) : "f"(a.z));
            asm("mov.b64 %0,{%1,%1};" : "=l"(da3) : "f"(a.w));
#pragma unroll
            for (int j = 0; j < 4; j++) {
                asm("fma.rn.f32x2 %0,%1,%2,%0;" : "+l"(acc2[r][j]) : "l"(da0), "l"(w0[j]));
                asm("fma.rn.f32x2 %0,%1,%2,%0;" : "+l"(acc2[r][j]) : "l"(da1), "l"(w1[j]));
                asm("fma.rn.f32x2 %0,%1,%2,%0;" : "+l"(acc2[r][j]) : "l"(da2), "l"(w2[j]));
                asm("fma.rn.f32x2 %0,%1,%2,%0;" : "+l"(acc2[r][j]) : "l"(da3), "l"(w3[j]));
            }
        }
    }
    // epilogue: fp8 store + per-head als/ald
    float as_[8], ad_[8];
#pragma unroll
    for (int j = 0; j < 4; j++) {
        float2 s2 = *(const float2*)&a_src[j * 32 + cg * 2];
        float2 d2 = *(const float2*)&a_dst[j * 32 + cg * 2];
        as_[2 * j] = s2.x; as_[2 * j + 1] = s2.y;
        ad_[2 * j] = d2.x; ad_[2 * j + 1] = d2.y;
    }
#pragma unroll
    for (int r = 0; r < 8; r++) {
        int row = row0 + r0 + r;
        float e[8];
#pragma unroll
        for (int j = 0; j < 4; j++) {
            float lo, hi;
            asm("mov.b64 {%0,%1},%2;" : "=f"(lo), "=f"(hi) : "l"(acc2[r][j]));
            e[2 * j] = lo; e[2 * j + 1] = hi;
        }
        float ps[4], pd[4];
#pragma unroll
        for (int j = 0; j < 4; j++) {
            ps[j] = e[2 * j] * as_[2 * j] + e[2 * j + 1] * as_[2 * j + 1];
            pd[j] = e[2 * j] * ad_[2 * j] + e[2 * j + 1] * ad_[2 * j + 1];
        }
#pragma unroll
        for (int m = 1; m < 16; m <<= 1) {
#pragma unroll
            for (int j = 0; j < 4; j++) {
                ps[j] += __shfl_xor_sync(0xffffffffu, ps[j], m);
                pd[j] += __shfl_xor_sync(0xffffffffu, pd[j], m);
            }
        }
        if (row < N) {
#pragma unroll
            for (int j = 0; j < 4; j++) {
                unsigned short b0 = __nv_cvt_float_to_fp8(e[2 * j] * scale, __NV_SATFINITE, __NV_E4M3);
                unsigned short b1 = __nv_cvt_float_to_fp8(e[2 * j + 1] * scale, __NV_SATFINITE, __NV_E4M3);
                *(unsigned short*)&g_hw8[(size_t)row * 128 + j * 32 + cg * 2] =
                    (unsigned short)(b0 | (b1 << 8));
            }
            if (cg == 0) {
                *(float4*)&g_als[row * 4] = make_float4(ps[0], ps[1], ps[2], ps[3]);
                *(float4*)&g_ald[row * 4] = make_float4(pd[0], pd[1], pd[2], pd[3]);
            }
        }
    }
}

// ---------------- layer-1 GEMM (input x) ----------------
__global__ void __launch_bounds__(256, 1)
k_gemm(const float* __restrict__ A, const float* __restrict__ W,
       const float* __restrict__ a_src, const float* __restrict__ a_dst,
       int N, float scale) {
    extern __shared__ float smem[];
    float* sx = smem;
    float* sw = smem + 16384;
    int tx = threadIdx.x;
    int row0 = blockIdx.x * 128;
    float4* sx4 = (float4*)sx;
    float4* sw4 = (float4*)sw;
    const float4* A4 = (const float4*)A;
    const float4* W4 = (const float4*)W;
#pragma unroll
    for (int i = tx; i < 4096; i += 256) {
        int r = i >> 5;
        sx4[i] = (row0 + r < N) ? A4[(size_t)(row0 + r) * 32 + (i & 31)]
                                : make_float4(0.f, 0.f, 0.f, 0.f);
        sw4[i] = W4[i];
    }
    __syncthreads();
    gemm_core(sx, sw, a_src, a_dst, row0, N, scale);
}

// ---------------- fused: layer-1 ngp (softmax+gate+pool) + layer-2 GEMM -------
__global__ void __launch_bounds__(256, 1)
k_ngp_gemm(const void* __restrict__ batch, const float* __restrict__ gate_w,
           const float* __restrict__ gate_b, const float* __restrict__ W,
           const float* __restrict__ a_src, const float* __restrict__ a_dst,
           int N, float scale) {
    extern __shared__ float smem[];
    float* sx = smem;
    float* sw = smem + 16384;
    float* sge = smem + 32768;
    int* sgid = (int*)(smem + 32896);
    int tx = threadIdx.x;
    int lane = tx & 31;
    int row0 = blockIdx.x * 128;
    int f64 = g_idx64;
    float4* sx4 = (float4*)sx;
    float4* sw4 = (float4*)sw;
    const float4* W4 = (const float4*)W;
    const float4* acc4 = (const float4*)g_acc;
#pragma unroll
    for (int i = tx; i < 4096; i += 256) {
        int r = i >> 5, c = i & 31;
        int row = row0 + r;
        if (row < N) {
            int g = load_idx(batch, row, f64);
            if (c == 0) sgid[r] = g;
            float4 e = acc4[(size_t)row * 32 + c];
            float4 cs = ((const float4*)(g_colsum + g * 128))[c];
            sx4[i] = make_float4(__fdividef(e.x, cs.x), __fdividef(e.y, cs.y),
                                 __fdividef(e.z, cs.z), __fdividef(e.w, cs.w));
        } else {
            if (c == 0) sgid[r] = 0;
            sx4[i] = make_float4(0.f, 0.f, 0.f, 0.f);
        }
        sw4[i] = W4[i];
    }
    __syncthreads();
    float4 gw = ((const float4*)gate_w)[lane];
#pragma unroll
    for (int j = 0; j < 16; j++) {
        int r = (tx >> 5) + 8 * j;
        float4 hs = sx4[r * 32 + lane];
        float p = hs.x * gw.x + hs.y * gw.y + hs.z * gw.z + hs.w * gw.w;
#pragma unroll
        for (int m = 16; m; m >>= 1) p += __shfl_xor_sync(0xffffffffu, p, m);
        if (lane == 0) sge[r] = p;
    }
    __syncthreads();
    if (tx < 128) {
        float ge = __expf(sge[tx] + gate_b[0]);
        sge[tx] = ge;
        if (row0 + tx < N) atomicAdd(&g_gatesum[sgid[tx]], ge);
    }
    __syncthreads();
#pragma unroll
    for (int j = 0; j < 16; j++) {
        int r = (tx >> 5) + 8 * j;
        int row = row0 + r;
        if (row < N) {
            float ge = sge[r];
            float4 hs = sx4[r * 32 + lane];
            red_add_v4(g_num + sgid[r] * 128 + lane * 4,
                       ge * hs.x, ge * hs.y, ge * hs.z, ge * hs.w);
        }
    }
    gemm_core(sx, sw, a_src, a_dst, row0, N, scale);
}

// ---------------- aggregation: warp per dst (CSR gather, fp8 rows) ----------
__global__ void k_agg(const float* __restrict__ bvec, const void* __restrict__ batch,
                      int N, float invscale) {
    int n = blockIdx.x * 8 + (threadIdx.x >> 5);
    int lane = threadIdx.x & 31;
    if (n >= N) return;
    const unsigned FULL = 0xffffffffu;
    int hf = lane >> 3;
    int hq = lane & 3;
    float ald_q = g_ald[n * 4 + hq];
    float lg = g_als[n * 4 + hq] + ald_q;
    lg = lg > 0.f ? lg : 0.2f * lg;
    float wq = __expf(lg);
    float ssum_q = wq;
    float wf = __shfl_sync(FULL, wq, hf);
    float4 v = ldrow8(n, lane);
    float4 acc = make_float4(wf * v.x, wf * v.y, wf * v.z, wf * v.w);

    int beg = g_off[n], end = g_off[n + 1];
    for (int j = beg; j < end; j += 8) {
        int rem = end - j;
        int et = lane >> 2;
        int s_e = 0; float wv = 0.f;
        if (et < rem) {
            s_e = g_csr[j + et];
            float l2 = g_als[s_e * 4 + hq] + ald_q;
            l2 = l2 > 0.f ? l2 : 0.2f * l2;
            wv = __expf(l2);
        }
        ssum_q += wv;
#pragma unroll
        for (int t = 0; t < 8; t++) {
            float w = __shfl_sync(FULL, wv, t * 4 + hf);
            int s = __shfl_sync(FULL, s_e, t * 4);
            float4 u = ldrow8(s, lane);
            acc.x += w * u.x; acc.y += w * u.y; acc.z += w * u.z; acc.w += w * u.w;
        }
    }
#pragma unroll
    for (int off = 4; off < 32; off <<= 1) ssum_q += __shfl_xor_sync(FULL, ssum_q, off);
    float inv = __fdividef(invscale, __shfl_sync(FULL, ssum_q, hf));

    float4 b = ((const float4*)bvec)[lane];
    float4 u;
    u.x = fmaxf(acc.x * inv + b.x, 0.f);
    u.y = fmaxf(acc.y * inv + b.y, 0.f);
    u.z = fmaxf(acc.z * inv + b.z, 0.f);
    u.w = fmaxf(acc.w * inv + b.w, 0.f);
    float4 ev = make_float4(__expf(u.x), __expf(u.y), __expf(u.z), __expf(u.w));
    ((float4*)(g_acc + (size_t)n * 128))[lane] = ev;
    int g = load_idx(batch, n, g_idx64);
    red_add_v4(g_colsum + g * 128 + lane * 4, ev.x, ev.y, ev.z, ev.w);
}

// ---------------- layer-2: softmax + gate + pool ----------------
__global__ void k_ngp(const void* __restrict__ batch, const float* __restrict__ gate_w,
                      const float* __restrict__ gate_b, int N) {
    int t = blockIdx.x * blockDim.x + threadIdx.x;
    int n = t >> 5, lane = t & 31;
    if (n >= N) return;
    const unsigned FULL = 0xffffffffu;
    int g = load_idx(batch, n, g_idx64);
    float4 e = ((const float4*)(g_acc + (size_t)n * 128))[lane];
    float4 c = ((const float4*)(g_colsum + g * 128))[lane];
    float4 hs = make_float4(__fdividef(e.x, c.x), __fdividef(e.y, c.y),
                            __fdividef(e.z, c.z), __fdividef(e.w, c.w));
    float4 gw = ((const float4*)gate_w)[lane];
    float p = hs.x * gw.x + hs.y * gw.y + hs.z * gw.z + hs.w * gw.w;
#pragma unroll
    for (int off = 16; off; off >>= 1) p += __shfl_xor_sync(FULL, p, off);
    float ge = __expf(p + gate_b[0]);
    red_add_v4(g_num + g * 128 + lane * 4, ge * hs.x, ge * hs.y, ge * hs.z, ge * hs.w);
    if (lane == 0) atomicAdd(&g_gatesum[g], ge);
}

// finalize after layer 1 (also zeroes per-layer accumulators for layer 2)
__global__ void k_fin() {
    int t = blockIdx.x * blockDim.x + threadIdx.x;
    if (t < GNUM * FDIM) {
        g_hg[t] += g_num[t] * __fdividef(1.f, g_gatesum[t >> 7]);
        g_num[t] = 0.f;
        g_colsum[t] = 0.f;
    }
    if (t < GNUM) g_gatesum[t] = 0.f;
}

// ---------------- MLP head (with fused layer-2 finalize) ----------------
__global__ void k_head(const float* __restrict__ lin_w, const float* __restrict__ lin_b,
                       const float* __restrict__ cls_w, const float* __restrict__ cls_b,
                       float* __restrict__ out) {
    int g = blockIdx.x;
    int j = threadIdx.x;
    __shared__ float shg[FDIM];
    __shared__ float sh[HID2];
    float invgs = __fdividef(1.f, g_gatesum[g]);
#pragma unroll
    for (int r = 0; r < 2; r++) {
        int k = j + r * HID2;
        shg[k] = g_hg[g * 128 + k] + g_num[g * 128 + k] * invgs;
    }
    __syncthreads();
    float a = lin_b[j];
#pragma unroll 4
    for (int k = 0; k < 128; k++) a += shg[k] * lin_w[k * HID2 + j];
    sh[j] = fmaxf(a, 0.f);
    __syncthreads();
    if (j < OUTD) {
        float o = cls_b[j];
#pragma unroll
        for (int k = 0; k < HID2; k++) o += sh[k] * cls_w[k * OUTD + j];
        out[g * OUTD + j] = o;
    }
}

// ---------------- launch ----------------
extern "C" void kernel_launch(void* const* d_in, const int* in_sizes, int n_in,
                              void* d_out, int out_size) {
    const float* x      = (const float*)d_in[0];
    const void*  ei     = d_in[1];
    const void*  batch  = d_in[2];
    const float* W1     = (const float*)d_in[3];
    const float* as1    = (const float*)d_in[4];
    const float* ad1    = (const float*)d_in[5];
    const float* b1     = (const float*)d_in[6];
    const float* W2     = (const float*)d_in[7];
    const float* as2    = (const float*)d_in[8];
    const float* ad2    = (const float*)d_in[9];
    const float* b2     = (const float*)d_in[10];
    const float* gate_w = (const float*)d_in[11];
    const float* gate_b = (const float*)d_in[12];
    const float* lin_w  = (const float*)d_in[13];
    const float* lin_b  = (const float*)d_in[14];
    const float* cls_w  = (const float*)d_in[15];
    const float* cls_b  = (const float*)d_in[16];
    float* out = (float*)d_out;

    int N = in_sizes[0] / FDIM;
    long long E = (long long)in_sizes[1] / 2;

    int nodeBlocks = (N + 7) / 8;
    int edgeBlocks = (int)((E + 255) / 256);
    int scanBlocks = (N + 1023) / 1024;
    int gemmBlocks = (N + 127) / 128;
    int zgrid = (N > GNUM * FDIM ? N : GNUM * FDIM);

    size_t gemm_smem = 32768 * sizeof(float);
    size_t ngpg_smem = (32768 + 256) * sizeof(float);

    // one-time host-side resources (no device memory)
    static cudaStream_t s1 = nullptr;
    static cudaEvent_t evFork = nullptr, evJoin = nullptr;
    if (!s1) {
        cudaStreamCreateWithFlags(&s1, cudaStreamNonBlocking);
        cudaEventCreateWithFlags(&evFork, cudaEventDisableTiming);
        cudaEventCreateWithFlags(&evJoin, cudaEventDisableTiming);
        cudaFuncSetAttribute(k_gemm, cudaFuncAttributeMaxDynamicSharedMemorySize, (int)gemm_smem);
        cudaFuncSetAttribute(k_ngp_gemm, cudaFuncAttributeMaxDynamicSharedMemorySize, (int)ngpg_smem);
    }

    // fork: layer-1 GEMM on s1, CSR build on main stream
    cudaEventRecord(evFork, 0);
    cudaStreamWaitEvent(s1, evFork, 0);
    k_gemm<<<gemmBlocks, 256, gemm_smem, s1>>>(x, W1, as1, ad1, N, 1.0f);
    cudaEventRecord(evJoin, s1);

    k_zero_pre<<<(zgrid + 255) / 256, 256>>>(ei, N);
    k_prep<<<edgeBlocks, 256>>>(ei, E);
    k_scan1<<<scanBlocks, 1024>>>(N);
    k_scan3<<<scanBlocks, 1024>>>(scanBlocks, N);
    k_fill<<<edgeBlocks, 256>>>(E);

    // join: agg needs CSR (main) + GEMM (s1)
    cudaStreamWaitEvent(0, evJoin, 0);

    // ---- layer 1 (fp8 rows, scale 1) ----
    k_agg<<<nodeBlocks, 256>>>(b1, batch, N, 1.0f);
    // ---- layer-1 pool + layer-2 GEMM (fp8 rows, scale 64) ----
    k_ngp_gemm<<<gemmBlocks, 256, ngpg_smem>>>(batch, gate_w, gate_b, W2, as2, ad2, N, 64.0f);
    k_fin<<<(GNUM * FDIM + 255) / 256, 256>>>();

    // ---- layer 2 ----
    k_agg<<<nodeBlocks, 256>>>(b2, batch, N, 1.0f / 64.0f);
    k_ngp<<<nodeBlocks, 256>>>(batch, gate_w, gate_b, N);

    // head (fused layer-2 finalize)
    k_head<<<GNUM, HID2>>>(lin_w, lin_b, cls_w, cls_b, out);
}